// round 10
// baseline (speedup 1.0000x reference)
#include <cuda_runtime.h>
#include <math.h>

// MultiActorCriticRNN: A=4, T=128, B=256, OBS=H=128, ACT=8
#define NA   4
#define NT   128
#define NB   256
#define NH   128
#define NOBS 128
#define NACT 8
#define G3   384   // 3*H

// Output layout: hT [A,B,H] | mean [A,T,B,ACT] | std [A,ACT] | value [A,T,B]
#define O_HT   0
#define O_MEAN 131072
#define O_STD  1179648
#define O_VAL  1179680

// Scratch (static device globals -- allocation-free kernel_launch)
__device__ float g_xi[(size_t)NA * NT * NB * G3];   // 50,331,648 floats
__device__ float g_ys[(size_t)NA * NT * NB * NH];   // 16,777,216 floats
__device__ int   g_done_mode;                       // 0=int32, 1=u8/bool, 2=float32

// ---------------------------------------------------------------------------
// done-dtype detection: scan the first N/4 words (= first N bytes, in-bounds
// for any element size >= 1 byte).
//   word == 0x3F800000           -> float32 (1.0f)
//   word > 1 && != 0x3F800000    -> byte-packed bool/uint8
//   all words in {0,1}           -> int32
// Recomputed fresh every launch (k_dzero then k_ddet) => deterministic.
// ---------------------------------------------------------------------------
__global__ void k_dzero() { g_done_mode = 0; }

__global__ void k_ddet(const unsigned int* __restrict__ w, int nwords)
{
    int mode = 0;
    for (int i = blockIdx.x * blockDim.x + threadIdx.x; i < nwords;
         i += gridDim.x * blockDim.x) {
        unsigned int v = w[i];
        if (v > 1u) mode = (v == 0x3F800000u) ? 2 : ((mode == 2) ? 2 : 1);
    }
    if (mode) atomicMax(&g_done_mode, mode);
}

__device__ __forceinline__ float read_done(const void* done, size_t idx, int mode)
{
    if (mode == 1) return ((const unsigned char*)done)[idx] ? 1.f : 0.f;
    if (mode == 2) return (((const float*)done)[idx] != 0.f) ? 1.f : 0.f;
    return ((const int*)done)[idx] ? 1.f : 0.f;
}

// ---------------------------------------------------------------------------
// 64x64 output tile, K=128 microkernel. Xs: [64][132] padded, Ws: [128][64].
// 256 threads as 16x16; each thread computes a 4x4 register tile.
// ---------------------------------------------------------------------------
__device__ __forceinline__ void mm_tile(const float* __restrict__ Xs,
                                        const float* __restrict__ Ws,
                                        float acc[4][4], int ty, int tx)
{
    const int r0 = 4 * ty, c0 = 4 * tx;
#pragma unroll 8
    for (int k = 0; k < 128; k += 4) {
        float4 x[4], w[4];
#pragma unroll
        for (int i = 0; i < 4; i++) x[i] = *(const float4*)&Xs[(r0 + i) * 132 + k];
#pragma unroll
        for (int i = 0; i < 4; i++) w[i] = *(const float4*)&Ws[(k + i) * 64 + c0];
        const float* xv = (const float*)x;
        const float* wv = (const float*)w;
#pragma unroll
        for (int kk = 0; kk < 4; kk++)
#pragma unroll
            for (int i = 0; i < 4; i++)
#pragma unroll
                for (int j = 0; j < 4; j++)
                    acc[i][j] = fmaf(xv[i * 4 + kk], wv[kk * 4 + j], acc[i][j]);
    }
}

// ---------------------------------------------------------------------------
// K1: xi = tanh(obs @ We + be) @ Wi + bi     -> g_xi
// grid (512, 4) : x = 64-row tile of T*B, y = agent. 256 threads.
// smem: obs_s[64][132] | emb_s[64][132] | w_s[128][64]
// ---------------------------------------------------------------------------
__global__ void __launch_bounds__(256)
k_embed(const float* __restrict__ obs, const float* __restrict__ We,
        const float* __restrict__ be,  const float* __restrict__ Wi,
        const float* __restrict__ bi)
{
    extern __shared__ float sm[];
    float* obs_s = sm;                    // 64*132
    float* emb_s = obs_s + 64 * 132;      // 64*132
    float* w_s   = emb_s + 64 * 132;      // 128*64

    const int a   = blockIdx.y;
    const int r0  = blockIdx.x * 64;      // row within T*B
    const int tid = threadIdx.x;
    const int ty  = tid >> 4, tx = tid & 15;

    // load obs tile (coalesced float4)
    const float* obsA = obs + ((size_t)a * NT * NB + r0) * NOBS;
    for (int i = tid; i < 64 * 32; i += 256) {
        int r = i >> 5, c4 = i & 31;
        ((float4*)&obs_s[r * 132])[c4] = ((const float4*)&obsA[(size_t)r * 128])[c4];
    }

    // stage 1: emb = tanh(obs @ We + be)
    const float* WeA = We + (size_t)a * 128 * 128;
    for (int cc = 0; cc < 2; cc++) {
        __syncthreads();
        for (int i = tid; i < 128 * 16; i += 256) {
            int k = i >> 4, c4 = i & 15;
            ((float4*)&w_s[k * 64])[c4] = ((const float4*)&WeA[k * 128 + cc * 64])[c4];
        }
        __syncthreads();
        float acc[4][4] = {};
        mm_tile(obs_s, w_s, acc, ty, tx);
#pragma unroll
        for (int i = 0; i < 4; i++)
#pragma unroll
            for (int j = 0; j < 4; j++) {
                int c = cc * 64 + 4 * tx + j;
                emb_s[(4 * ty + i) * 132 + c] = tanhf(acc[i][j] + be[a * 128 + c]);
            }
    }

    // stage 2: xi = emb @ Wi + bi
    const float* WiA = Wi + (size_t)a * 128 * G3;
    float* xiA = g_xi + ((size_t)a * NT * NB + r0) * G3;
    for (int cc = 0; cc < 6; cc++) {
        __syncthreads();
        for (int i = tid; i < 128 * 16; i += 256) {
            int k = i >> 4, c4 = i & 15;
            ((float4*)&w_s[k * 64])[c4] = ((const float4*)&WiA[k * G3 + cc * 64])[c4];
        }
        __syncthreads();
        float acc[4][4] = {};
        mm_tile(emb_s, w_s, acc, ty, tx);
#pragma unroll
        for (int i = 0; i < 4; i++)
#pragma unroll
            for (int j = 0; j < 4; j++) {
                int c = cc * 64 + 4 * tx + j;
                xiA[(size_t)(4 * ty + i) * G3 + c] = acc[i][j] + bi[a * G3 + c];
            }
    }
}

// ---------------------------------------------------------------------------
// K2: sequential GRU. grid (32, 4): x = 8-batch-row tile, y = agent. 256 thr.
// Wh resident in smem (192KB). Per-thread tile: 4 rows x (r,z,n) at column tx.
// Writes ys to g_ys and final h to out[O_HT].
// smem: Wh_s[128*384] | h_s[8][132] | xi_s[2][8][384] | bhn_s[128] | done_s[8]
// ---------------------------------------------------------------------------
__global__ void __launch_bounds__(256)
k_gru(const float* __restrict__ hstate, const float* __restrict__ Wh,
      const float* __restrict__ bhn, const void* __restrict__ done,
      float* __restrict__ out)
{
    extern __shared__ float sm[];
    float* Wh_s   = sm;                    // 49152
    float* h_s    = Wh_s + 128 * G3;       // 8*132 = 1056
    float* xi_s   = h_s + 8 * 132;         // 2*8*384 = 6144
    float* bhn_s  = xi_s + 2 * 8 * G3;     // 128
    float* done_s = bhn_s + 128;           // 8

    const int a   = blockIdx.y;
    const int b0  = blockIdx.x * 8;
    const int tid = threadIdx.x;
    const int ty  = tid >> 7;              // 0..1 -> rows 4*ty..
    const int tx  = tid & 127;             // column j
    const int dmode = g_done_mode;

    // load Wh for this agent
    const float* WhA = Wh + (size_t)a * 128 * G3;
    for (int i = tid; i < 128 * 96; i += 256)
        ((float4*)Wh_s)[i] = ((const float4*)WhA)[i];
    if (tid < 128) bhn_s[tid] = bhn[a * 128 + tid];

    // load h0
    for (int i = tid; i < 8 * 32; i += 256) {
        int r = i >> 5, c4 = i & 31;
        ((float4*)&h_s[r * 132])[c4] =
            ((const float4*)&hstate[((size_t)a * NB + b0 + r) * NH])[c4];
    }
    // preload xi for t = 0 into buffer 0
    {
        const float* xiA = g_xi + ((size_t)a * NT * NB + b0) * G3;
        for (int i = tid; i < 8 * 96; i += 256) {
            int r = i / 96, c4 = i % 96;
            ((float4*)&xi_s[r * G3])[c4] = ((const float4*)&xiA[(size_t)r * G3])[c4];
        }
    }
    __syncthreads();

    float* ysA = g_ys + ((size_t)a * NT * NB + b0) * NH;

    for (int t = 0; t < NT; t++) {
        // done mask (applied BEFORE h @ Wh, per reference)
        if (tid < 8)
            done_s[tid] =
                read_done(done, ((size_t)a * NT + t) * NB + b0 + tid, dmode);
        __syncthreads();
        for (int i = tid; i < 1024; i += 256) {
            int r = i >> 7, c = i & 127;
            if (done_s[r] != 0.f) h_s[r * 132 + c] = 0.f;
        }
        __syncthreads();

        // prefetch xi for t+1 into registers (hidden behind the k-loop)
        float4 pre[3];
        if (t + 1 < NT) {
            const float* xiN = g_xi + ((size_t)a * NT * NB + (size_t)(t + 1) * NB + b0) * G3;
#pragma unroll
            for (int i = 0; i < 3; i++) {
                int idx = tid + 256 * i;     // 0..767 float4 covering 8x384
                int r = idx / 96, c4 = idx % 96;
                pre[i] = ((const float4*)&xiN[(size_t)r * G3])[c4];
            }
        }

        // hh = h @ Wh for rows 4*ty..4*ty+3, cols {tx, 128+tx, 256+tx}
        float acc[4][3] = {};
        const float* hr = &h_s[4 * ty * 132];
#pragma unroll 4
        for (int k = 0; k < 128; k += 4) {
            float4 hv[4];
#pragma unroll
            for (int i = 0; i < 4; i++) hv[i] = *(const float4*)&hr[i * 132 + k];
            const float* hvv = (const float*)hv;
#pragma unroll
            for (int kk = 0; kk < 4; kk++) {
                float w0 = Wh_s[(k + kk) * G3 + tx];
                float w1 = Wh_s[(k + kk) * G3 + 128 + tx];
                float w2 = Wh_s[(k + kk) * G3 + 256 + tx];
#pragma unroll
                for (int i = 0; i < 4; i++) {
                    float hx = hvv[i * 4 + kk];
                    acc[i][0] = fmaf(hx, w0, acc[i][0]);
                    acc[i][1] = fmaf(hx, w1, acc[i][1]);
                    acc[i][2] = fmaf(hx, w2, acc[i][2]);
                }
            }
        }
        __syncthreads();   // all reads of h_s done

        // commit prefetched xi into the other buffer
        float* xin_s = xi_s + ((t + 1) & 1) * (8 * G3);
        const float* xic_s = xi_s + (t & 1) * (8 * G3);
        if (t + 1 < NT) {
#pragma unroll
            for (int i = 0; i < 3; i++) {
                int idx = tid + 256 * i;
                int r = idx / 96, c4 = idx % 96;
                ((float4*)&xin_s[r * G3])[c4] = pre[i];
            }
        }

        // gates (register-local per (row, j))
#pragma unroll
        for (int i = 0; i < 4; i++) {
            int r = 4 * ty + i;
            float xr = xic_s[r * G3 + tx];
            float xz = xic_s[r * G3 + 128 + tx];
            float xn = xic_s[r * G3 + 256 + tx];
            float hprev = h_s[r * 132 + tx];
            float rg = 1.f / (1.f + expf(-(xr + acc[i][0])));
            float zg = 1.f / (1.f + expf(-(xz + acc[i][1])));
            float ng = tanhf(xn + rg * (acc[i][2] + bhn_s[tx]));
            float hnew = (1.f - zg) * ng + zg * hprev;
            h_s[r * 132 + tx] = hnew;
            ysA[((size_t)t * NB + r) * NH + tx] = hnew;
        }
        __syncthreads();
    }

    // final hidden state
    for (int i = tid; i < 8 * 32; i += 256) {
        int r = i >> 5, c4 = i & 31;
        ((float4*)&out[O_HT + ((size_t)a * NB + b0 + r) * NH])[c4] =
            ((float4*)&h_s[r * 132])[c4];
    }
}

// ---------------------------------------------------------------------------
// K3: heads. grid (512, 4). 256 threads.
// a = tanh(ys@Wa1+ba1); mean = a@Wa2+ba2; c = tanh(ys@Wc1+bc1); value = c@Wc2+bc2
// smem: ys_s[64][132] | act_s[64][132] | w_s[128][64] | wsm_s[128*8]
// ---------------------------------------------------------------------------
__global__ void __launch_bounds__(256)
k_heads(const float* __restrict__ Wa1, const float* __restrict__ ba1,
        const float* __restrict__ Wa2, const float* __restrict__ ba2,
        const float* __restrict__ Wc1, const float* __restrict__ bc1,
        const float* __restrict__ Wc2, const float* __restrict__ bc2,
        const float* __restrict__ log_std, float* __restrict__ out)
{
    extern __shared__ float sm[];
    float* ys_s  = sm;                    // 64*132
    float* act_s = ys_s + 64 * 132;       // 64*132
    float* w_s   = act_s + 64 * 132;      // 128*64
    float* wsm_s = w_s + 128 * 64;        // 1024 (Wa2 then Wc2)

    const int a   = blockIdx.y;
    const int r0  = blockIdx.x * 64;
    const int tid = threadIdx.x;
    const int ty  = tid >> 4, tx = tid & 15;

    if (blockIdx.x == 0 && blockIdx.y == 0 && tid < NA * NACT)
        out[O_STD + tid] = expf(log_std[tid]);

    // load ys tile
    const float* ysA = g_ys + ((size_t)a * NT * NB + r0) * NH;
    for (int i = tid; i < 64 * 32; i += 256) {
        int r = i >> 5, c4 = i & 31;
        ((float4*)&ys_s[r * 132])[c4] = ((const float4*)&ysA[(size_t)r * 128])[c4];
    }

    // actor hidden
    const float* Wa1A = Wa1 + (size_t)a * 128 * 128;
    for (int cc = 0; cc < 2; cc++) {
        __syncthreads();
        for (int i = tid; i < 128 * 16; i += 256) {
            int k = i >> 4, c4 = i & 15;
            ((float4*)&w_s[k * 64])[c4] = ((const float4*)&Wa1A[k * 128 + cc * 64])[c4];
        }
        __syncthreads();
        float acc[4][4] = {};
        mm_tile(ys_s, w_s, acc, ty, tx);
#pragma unroll
        for (int i = 0; i < 4; i++)
#pragma unroll
            for (int j = 0; j < 4; j++) {
                int c = cc * 64 + 4 * tx + j;
                act_s[(4 * ty + i) * 132 + c] = tanhf(acc[i][j] + ba1[a * 128 + c]);
            }
    }
    __syncthreads();
    // Wa2 to smem
    for (int i = tid; i < 128 * 2; i += 256)
        ((float4*)wsm_s)[i] = ((const float4*)(Wa2 + (size_t)a * 128 * NACT))[i];
    __syncthreads();
    // mean: 64 rows x 8 actions
    for (int o = tid; o < 512; o += 256) {
        int r = o >> 3, ac = o & 7;
        float s = ba2[a * NACT + ac];
#pragma unroll 8
        for (int k = 0; k < 128; k++)
            s = fmaf(act_s[r * 132 + k], wsm_s[k * 8 + ac], s);
        out[O_MEAN + ((size_t)a * NT * NB + r0 + r) * NACT + ac] = s;
    }

    // critic hidden (reuse act_s after sync)
    const float* Wc1A = Wc1 + (size_t)a * 128 * 128;
    for (int cc = 0; cc < 2; cc++) {
        __syncthreads();
        for (int i = tid; i < 128 * 16; i += 256) {
            int k = i >> 4, c4 = i & 15;
            ((float4*)&w_s[k * 64])[c4] = ((const float4*)&Wc1A[k * 128 + cc * 64])[c4];
        }
        __syncthreads();
        float acc[4][4] = {};
        mm_tile(ys_s, w_s, acc, ty, tx);
#pragma unroll
        for (int i = 0; i < 4; i++)
#pragma unroll
            for (int j = 0; j < 4; j++) {
                int c = cc * 64 + 4 * tx + j;
                act_s[(4 * ty + i) * 132 + c] = tanhf(acc[i][j] + bc1[a * 128 + c]);
            }
    }
    __syncthreads();
    if (tid < 128) wsm_s[tid] = Wc2[(size_t)a * 128 + tid];
    __syncthreads();
    if (tid < 64) {
        float s = bc2[a];
#pragma unroll 8
        for (int k = 0; k < 128; k++)
            s = fmaf(act_s[tid * 132 + k], wsm_s[k], s);
        out[O_VAL + (size_t)a * NT * NB + r0 + tid] = s;
    }
}

// ---------------------------------------------------------------------------
extern "C" void kernel_launch(void* const* d_in, const int* in_sizes, int n_in,
                              void* d_out, int out_size)
{
    const float* hstate  = (const float*)d_in[0];
    const float* obs     = (const float*)d_in[1];
    // d_in[2] = avail_actions (unused by the reference outputs)
    const float* We      = (const float*)d_in[3];
    const float* be      = (const float*)d_in[4];
    const float* Wi      = (const float*)d_in[5];
    const float* bi      = (const float*)d_in[6];
    const float* Wh      = (const float*)d_in[7];
    const float* bhn     = (const float*)d_in[8];
    const float* Wa1     = (const float*)d_in[9];
    const float* ba1     = (const float*)d_in[10];
    const float* Wa2     = (const float*)d_in[11];
    const float* ba2     = (const float*)d_in[12];
    const float* log_std = (const float*)d_in[13];
    const float* Wc1     = (const float*)d_in[14];
    const float* bc1     = (const float*)d_in[15];
    const float* Wc2     = (const float*)d_in[16];
    const float* bc2     = (const float*)d_in[17];
    const void*  done    = d_in[18];
    float* out = (float*)d_out;

    const int SMEM1 = (64 * 132 * 2 + 128 * 64) * 4;                       // 100352
    const int SMEM2 = (128 * G3 + 8 * 132 + 2 * 8 * G3 + 128 + 8) * 4;     // 225952
    const int SMEM3 = (64 * 132 * 2 + 128 * 64 + 1024) * 4;                // 104448

    cudaFuncSetAttribute(k_embed, cudaFuncAttributeMaxDynamicSharedMemorySize, SMEM1);
    cudaFuncSetAttribute(k_gru,   cudaFuncAttributeMaxDynamicSharedMemorySize, SMEM2);
    cudaFuncSetAttribute(k_heads, cudaFuncAttributeMaxDynamicSharedMemorySize, SMEM3);

    // detect done dtype (first N bytes read as words; safe for any elem size)
    const int n_done = in_sizes[18];           // A*T*B elements
    k_dzero<<<1, 1>>>();
    k_ddet<<<32, 256>>>((const unsigned int*)done, n_done / 4);

    k_embed<<<dim3(512, 4), 256, SMEM1>>>(obs, We, be, Wi, bi);
    k_gru  <<<dim3(32, 4),  256, SMEM2>>>(hstate, Wh, bhn, done, out);
    k_heads<<<dim3(512, 4), 256, SMEM3>>>(Wa1, ba1, Wa2, ba2, Wc1, bc1, Wc2, bc2,
                                          log_std, out);
}

// round 11
// speedup vs baseline: 1.0621x; 1.0621x over previous
#include <cuda_runtime.h>
#include <math.h>

// MultiActorCriticRNN: A=4, T=128, B=256, OBS=H=128, ACT=8
#define NA   4
#define NT   128
#define NB   256
#define NH   128
#define NOBS 128
#define NACT 8
#define G3   384   // 3*H

// Output layout: hT [A,B,H] | mean [A,T,B,ACT] | std [A,ACT] | value [A,T,B]
#define O_HT   0
#define O_MEAN 131072
#define O_STD  1179648
#define O_VAL  1179680

// Scratch (static device globals -- allocation-free kernel_launch)
__device__ float g_xi[(size_t)NA * NT * NB * G3];   // 50,331,648 floats
__device__ float g_ys[(size_t)NA * NT * NB * NH];   // 16,777,216 floats
__device__ int   g_done_mode;                       // 0=int32, 1=u8/bool, 2=float32

// ---------------------------------------------------------------------------
// done-dtype detection (recomputed fresh every launch => deterministic)
// ---------------------------------------------------------------------------
__global__ void k_dzero() { g_done_mode = 0; }

__global__ void k_ddet(const unsigned int* __restrict__ w, int nwords)
{
    int mode = 0;
    for (int i = blockIdx.x * blockDim.x + threadIdx.x; i < nwords;
         i += gridDim.x * blockDim.x) {
        unsigned int v = w[i];
        if (v > 1u) mode = (v == 0x3F800000u) ? 2 : ((mode == 2) ? 2 : 1);
    }
    if (mode) atomicMax(&g_done_mode, mode);
}

__device__ __forceinline__ float read_done(const void* done, size_t idx, int mode)
{
    if (mode == 1) return ((const unsigned char*)done)[idx] ? 1.f : 0.f;
    if (mode == 2) return (((const float*)done)[idx] != 0.f) ? 1.f : 0.f;
    return ((const int*)done)[idx] ? 1.f : 0.f;
}

// ---------------------------------------------------------------------------
// 64x64 output tile, K=128 microkernel. Xs: [64][132] padded, Ws: [128][64].
// ---------------------------------------------------------------------------
__device__ __forceinline__ void mm_tile(const float* __restrict__ Xs,
                                        const float* __restrict__ Ws,
                                        float acc[4][4], int ty, int tx)
{
    const int r0 = 4 * ty, c0 = 4 * tx;
#pragma unroll 8
    for (int k = 0; k < 128; k += 4) {
        float4 x[4], w[4];
#pragma unroll
        for (int i = 0; i < 4; i++) x[i] = *(const float4*)&Xs[(r0 + i) * 132 + k];
#pragma unroll
        for (int i = 0; i < 4; i++) w[i] = *(const float4*)&Ws[(k + i) * 64 + c0];
        const float* xv = (const float*)x;
        const float* wv = (const float*)w;
#pragma unroll
        for (int kk = 0; kk < 4; kk++)
#pragma unroll
            for (int i = 0; i < 4; i++)
#pragma unroll
                for (int j = 0; j < 4; j++)
                    acc[i][j] = fmaf(xv[i * 4 + kk], wv[kk * 4 + j], acc[i][j]);
    }
}

// ---------------------------------------------------------------------------
// K1: xi = tanh(obs @ We + be) @ Wi + bi     -> g_xi
// ---------------------------------------------------------------------------
__global__ void __launch_bounds__(256)
k_embed(const float* __restrict__ obs, const float* __restrict__ We,
        const float* __restrict__ be,  const float* __restrict__ Wi,
        const float* __restrict__ bi)
{
    extern __shared__ float sm[];
    float* obs_s = sm;                    // 64*132
    float* emb_s = obs_s + 64 * 132;      // 64*132
    float* w_s   = emb_s + 64 * 132;      // 128*64

    const int a   = blockIdx.y;
    const int r0  = blockIdx.x * 64;
    const int tid = threadIdx.x;
    const int ty  = tid >> 4, tx = tid & 15;

    const float* obsA = obs + ((size_t)a * NT * NB + r0) * NOBS;
    for (int i = tid; i < 64 * 32; i += 256) {
        int r = i >> 5, c4 = i & 31;
        ((float4*)&obs_s[r * 132])[c4] = ((const float4*)&obsA[(size_t)r * 128])[c4];
    }

    const float* WeA = We + (size_t)a * 128 * 128;
    for (int cc = 0; cc < 2; cc++) {
        __syncthreads();
        for (int i = tid; i < 128 * 16; i += 256) {
            int k = i >> 4, c4 = i & 15;
            ((float4*)&w_s[k * 64])[c4] = ((const float4*)&WeA[k * 128 + cc * 64])[c4];
        }
        __syncthreads();
        float acc[4][4] = {};
        mm_tile(obs_s, w_s, acc, ty, tx);
#pragma unroll
        for (int i = 0; i < 4; i++)
#pragma unroll
            for (int j = 0; j < 4; j++) {
                int c = cc * 64 + 4 * tx + j;
                emb_s[(4 * ty + i) * 132 + c] = tanhf(acc[i][j] + be[a * 128 + c]);
            }
    }

    const float* WiA = Wi + (size_t)a * 128 * G3;
    float* xiA = g_xi + ((size_t)a * NT * NB + r0) * G3;
    for (int cc = 0; cc < 6; cc++) {
        __syncthreads();
        for (int i = tid; i < 128 * 16; i += 256) {
            int k = i >> 4, c4 = i & 15;
            ((float4*)&w_s[k * 64])[c4] = ((const float4*)&WiA[k * G3 + cc * 64])[c4];
        }
        __syncthreads();
        float acc[4][4] = {};
        mm_tile(emb_s, w_s, acc, ty, tx);
#pragma unroll
        for (int i = 0; i < 4; i++)
#pragma unroll
            for (int j = 0; j < 4; j++) {
                int c = cc * 64 + 4 * tx + j;
                xiA[(size_t)(4 * ty + i) * G3 + c] = acc[i][j] + bi[a * G3 + c];
            }
    }
}

// ---------------------------------------------------------------------------
// K2: sequential GRU. grid (32, 4): x = 8-batch-row tile, y = agent. 256 thr.
// Wh resident in smem. Two independent 128-thread halves (4 rows each),
// synced by named barriers only. done folded into registers (scales acc and
// hprev). xi read straight from gmem into registers each step (latency
// hidden under the 128-deep k-loop).
// smem: Wh_s[128*384] | h_s[8][132] | bhn_s[128]
// ---------------------------------------------------------------------------
__global__ void __launch_bounds__(256)
k_gru(const float* __restrict__ hstate, const float* __restrict__ Wh,
      const float* __restrict__ bhn, const void* __restrict__ done,
      float* __restrict__ out)
{
    extern __shared__ float sm[];
    float* Wh_s  = sm;                    // 128*384
    float* h_s   = Wh_s + 128 * G3;       // 8*132
    float* bhn_s = h_s + 8 * 132;         // 128

    const int a   = blockIdx.y;
    const int b0  = blockIdx.x * 8;
    const int tid = threadIdx.x;
    const int ty  = tid >> 7;              // half: rows 4*ty..4*ty+3
    const int tx  = tid & 127;             // column j
    const int dmode = g_done_mode;

    // load Wh + bhn + h0
    const float* WhA = Wh + (size_t)a * 128 * G3;
    for (int i = tid; i < 128 * 96; i += 256)
        ((float4*)Wh_s)[i] = ((const float4*)WhA)[i];
    if (tid < 128) bhn_s[tid] = bhn[a * 128 + tid];
    for (int i = tid; i < 8 * 32; i += 256) {
        int r = i >> 5, c4 = i & 31;
        ((float4*)&h_s[r * 132])[c4] =
            ((const float4*)&hstate[((size_t)a * NB + b0 + r) * NH])[c4];
    }
    __syncthreads();

    const int bar = 1 + ty;                // named barrier per half
    float* ysA = g_ys + ((size_t)a * NT * NB + b0) * NH;
    const float bh = bhn_s[tx];

    for (int t = 0; t < NT; t++) {
        // per-row done mask -> registers (L1-broadcast LDG, hidden by k-loop)
        float m[4];
#pragma unroll
        for (int i = 0; i < 4; i++)
            m[i] = 1.f - read_done(done,
                       ((size_t)a * NT + t) * NB + b0 + 4 * ty + i, dmode);

        // xi for my (row, col) tile -> registers (12 coalesced LDG)
        const float* xiT = g_xi + (((size_t)a * NT + t) * NB + b0 + 4 * ty) * G3;
        float xr[4], xz[4], xn[4];
#pragma unroll
        for (int i = 0; i < 4; i++) {
            xr[i] = xiT[(size_t)i * G3 + tx];
            xz[i] = xiT[(size_t)i * G3 + 128 + tx];
            xn[i] = xiT[(size_t)i * G3 + 256 + tx];
        }

        // hh = h @ Wh for rows 4*ty..4*ty+3, cols {tx, 128+tx, 256+tx}
        float acc[4][3] = {};
        const float* hr = &h_s[4 * ty * 132];
#pragma unroll 4
        for (int k = 0; k < 128; k += 4) {
            float4 hv[4];
#pragma unroll
            for (int i = 0; i < 4; i++) hv[i] = *(const float4*)&hr[i * 132 + k];
            const float* hvv = (const float*)hv;
#pragma unroll
            for (int kk = 0; kk < 4; kk++) {
                float w0 = Wh_s[(k + kk) * G3 + tx];
                float w1 = Wh_s[(k + kk) * G3 + 128 + tx];
                float w2 = Wh_s[(k + kk) * G3 + 256 + tx];
#pragma unroll
                for (int i = 0; i < 4; i++) {
                    float hx = hvv[i * 4 + kk];
                    acc[i][0] = fmaf(hx, w0, acc[i][0]);
                    acc[i][1] = fmaf(hx, w1, acc[i][1]);
                    acc[i][2] = fmaf(hx, w2, acc[i][2]);
                }
            }
        }
        asm volatile("bar.sync %0, 128;" :: "r"(bar) : "memory"); // reads done

        // gates; mask(h)@Wh == m * (h@Wh) since m is per-row scalar
#pragma unroll
        for (int i = 0; i < 4; i++) {
            int r = 4 * ty + i;
            float hprev = m[i] * h_s[r * 132 + tx];
            float rg = 1.f / (1.f + expf(-(xr[i] + m[i] * acc[i][0])));
            float zg = 1.f / (1.f + expf(-(xz[i] + m[i] * acc[i][1])));
            float ng = tanhf(xn[i] + rg * (m[i] * acc[i][2] + bh));
            float hnew = (1.f - zg) * ng + zg * hprev;
            h_s[r * 132 + tx] = hnew;
            ysA[((size_t)t * NB + r) * NH + tx] = hnew;
        }
        asm volatile("bar.sync %0, 128;" :: "r"(bar) : "memory"); // writes done
    }

    __syncthreads();
    for (int i = tid; i < 8 * 32; i += 256) {
        int r = i >> 5, c4 = i & 31;
        ((float4*)&out[O_HT + ((size_t)a * NB + b0 + r) * NH])[c4] =
            ((float4*)&h_s[r * 132])[c4];
    }
}

// ---------------------------------------------------------------------------
// K3: heads.
// ---------------------------------------------------------------------------
__global__ void __launch_bounds__(256)
k_heads(const float* __restrict__ Wa1, const float* __restrict__ ba1,
        const float* __restrict__ Wa2, const float* __restrict__ ba2,
        const float* __restrict__ Wc1, const float* __restrict__ bc1,
        const float* __restrict__ Wc2, const float* __restrict__ bc2,
        const float* __restrict__ log_std, float* __restrict__ out)
{
    extern __shared__ float sm[];
    float* ys_s  = sm;                    // 64*132
    float* act_s = ys_s + 64 * 132;       // 64*132
    float* w_s   = act_s + 64 * 132;      // 128*64
    float* wsm_s = w_s + 128 * 64;        // 1024

    const int a   = blockIdx.y;
    const int r0  = blockIdx.x * 64;
    const int tid = threadIdx.x;
    const int ty  = tid >> 4, tx = tid & 15;

    if (blockIdx.x == 0 && blockIdx.y == 0 && tid < NA * NACT)
        out[O_STD + tid] = expf(log_std[tid]);

    const float* ysA = g_ys + ((size_t)a * NT * NB + r0) * NH;
    for (int i = tid; i < 64 * 32; i += 256) {
        int r = i >> 5, c4 = i & 31;
        ((float4*)&ys_s[r * 132])[c4] = ((const float4*)&ysA[(size_t)r * 128])[c4];
    }

    const float* Wa1A = Wa1 + (size_t)a * 128 * 128;
    for (int cc = 0; cc < 2; cc++) {
        __syncthreads();
        for (int i = tid; i < 128 * 16; i += 256) {
            int k = i >> 4, c4 = i & 15;
            ((float4*)&w_s[k * 64])[c4] = ((const float4*)&Wa1A[k * 128 + cc * 64])[c4];
        }
        __syncthreads();
        float acc[4][4] = {};
        mm_tile(ys_s, w_s, acc, ty, tx);
#pragma unroll
        for (int i = 0; i < 4; i++)
#pragma unroll
            for (int j = 0; j < 4; j++) {
                int c = cc * 64 + 4 * tx + j;
                act_s[(4 * ty + i) * 132 + c] = tanhf(acc[i][j] + ba1[a * 128 + c]);
            }
    }
    __syncthreads();
    for (int i = tid; i < 128 * 2; i += 256)
        ((float4*)wsm_s)[i] = ((const float4*)(Wa2 + (size_t)a * 128 * NACT))[i];
    __syncthreads();
    for (int o = tid; o < 512; o += 256) {
        int r = o >> 3, ac = o & 7;
        float s = ba2[a * NACT + ac];
#pragma unroll 8
        for (int k = 0; k < 128; k++)
            s = fmaf(act_s[r * 132 + k], wsm_s[k * 8 + ac], s);
        out[O_MEAN + ((size_t)a * NT * NB + r0 + r) * NACT + ac] = s;
    }

    const float* Wc1A = Wc1 + (size_t)a * 128 * 128;
    for (int cc = 0; cc < 2; cc++) {
        __syncthreads();
        for (int i = tid; i < 128 * 16; i += 256) {
            int k = i >> 4, c4 = i & 15;
            ((float4*)&w_s[k * 64])[c4] = ((const float4*)&Wc1A[k * 128 + cc * 64])[c4];
        }
        __syncthreads();
        float acc[4][4] = {};
        mm_tile(ys_s, w_s, acc, ty, tx);
#pragma unroll
        for (int i = 0; i < 4; i++)
#pragma unroll
            for (int j = 0; j < 4; j++) {
                int c = cc * 64 + 4 * tx + j;
                act_s[(4 * ty + i) * 132 + c] = tanhf(acc[i][j] + bc1[a * 128 + c]);
            }
    }
    __syncthreads();
    if (tid < 128) wsm_s[tid] = Wc2[(size_t)a * 128 + tid];
    __syncthreads();
    if (tid < 64) {
        float s = bc2[a];
#pragma unroll 8
        for (int k = 0; k < 128; k++)
            s = fmaf(act_s[tid * 132 + k], wsm_s[k], s);
        out[O_VAL + (size_t)a * NT * NB + r0 + tid] = s;
    }
}

// ---------------------------------------------------------------------------
extern "C" void kernel_launch(void* const* d_in, const int* in_sizes, int n_in,
                              void* d_out, int out_size)
{
    const float* hstate  = (const float*)d_in[0];
    const float* obs     = (const float*)d_in[1];
    // d_in[2] = avail_actions (unused by the reference outputs)
    const float* We      = (const float*)d_in[3];
    const float* be      = (const float*)d_in[4];
    const float* Wi      = (const float*)d_in[5];
    const float* bi      = (const float*)d_in[6];
    const float* Wh      = (const float*)d_in[7];
    const float* bhn     = (const float*)d_in[8];
    const float* Wa1     = (const float*)d_in[9];
    const float* ba1     = (const float*)d_in[10];
    const float* Wa2     = (const float*)d_in[11];
    const float* ba2     = (const float*)d_in[12];
    const float* log_std = (const float*)d_in[13];
    const float* Wc1     = (const float*)d_in[14];
    const float* bc1     = (const float*)d_in[15];
    const float* Wc2     = (const float*)d_in[16];
    const float* bc2     = (const float*)d_in[17];
    const void*  done    = d_in[18];
    float* out = (float*)d_out;

    const int SMEM1 = (64 * 132 * 2 + 128 * 64) * 4;            // 100352
    const int SMEM2 = (128 * G3 + 8 * 132 + 128) * 4;           // 201344
    const int SMEM3 = (64 * 132 * 2 + 128 * 64 + 1024) * 4;     // 104448

    cudaFuncSetAttribute(k_embed, cudaFuncAttributeMaxDynamicSharedMemorySize, SMEM1);
    cudaFuncSetAttribute(k_gru,   cudaFuncAttributeMaxDynamicSharedMemorySize, SMEM2);
    cudaFuncSetAttribute(k_heads, cudaFuncAttributeMaxDynamicSharedMemorySize, SMEM3);

    const int n_done = in_sizes[18];
    k_dzero<<<1, 1>>>();
    k_ddet<<<32, 256>>>((const unsigned int*)done, n_done / 4);

    k_embed<<<dim3(512, 4), 256, SMEM1>>>(obs, We, be, Wi, bi);
    k_gru  <<<dim3(32, 4),  256, SMEM2>>>(hstate, Wh, bhn, done, out);
    k_heads<<<dim3(512, 4), 256, SMEM3>>>(Wa1, ba1, Wa2, ba2, Wc1, bc1, Wc2, bc2,
                                          log_std, out);
}